// round 2
// baseline (speedup 1.0000x reference)
#include <cuda_runtime.h>
#include <cuda_fp16.h>
#include <cstdint>

// ============================================================================
// QuantLinear: y = x @ (scales*q - zeros) + bias
//   x:[32,4096] f32, qweight:[512,11008] i32 (8 nibbles/word along K),
//   scales/zeros/bias:[11008] f32, out:[32,11008] f32
//
// sm_100 (portable) path: mma.sync.m16n8k16 fp16 -> f32.
//   prep:  g_A[32,4096] = fp16(x), g_S[32] = row sums of fp16(x)
//   gemm:  B dequant nibble n -> fp16(1024+n) directly into mma B-fragment
//          registers (thread t%4 owns exactly nibbles 2j,2j+1 of its kword).
//          Epilogue: y = s*D - S*(1024*s + z) + b
// ============================================================================

#define KTOT   4096
#define NTOT   11008
#define MTOK   32
#define TILE_N 128
#define TILE_K 128
#define NCHUNK (KTOT / TILE_K)   // 32
#define THREADS 256
#define STAGES 4

// stage: A = 32 rows x 256B = 8192B ; Q = 16 kwords x 512B = 8192B
#define STAGE_BYTES 16384
#define SM_CONST 0        // sc[128], bi[128], corr[128], S[32] floats
#define SM_STAGE0 2048
#define SMEM_TOTAL (SM_STAGE0 + STAGES * STAGE_BYTES)   // 67584

__device__ __half g_A[MTOK * KTOT];
__device__ float  g_S[MTOK];

// ---------------------------------------------------------------------------
__device__ __forceinline__ uint32_t smem_u32(const void* p) {
    uint32_t a;
    asm("{ .reg .u64 t; cvta.to.shared.u64 t, %1; cvt.u32.u64 %0, t; }"
        : "=r"(a) : "l"(p));
    return a;
}

#define CP16(dst, src) \
    asm volatile("cp.async.cg.shared.global [%0], [%1], 16;" :: "r"(dst), "l"(src))
#define CP_COMMIT() asm volatile("cp.async.commit_group;" ::: "memory")

__device__ __forceinline__ void mma16816(float* d, const uint32_t* a,
                                         uint32_t b0, uint32_t b1) {
    asm volatile(
        "mma.sync.aligned.m16n8k16.row.col.f32.f16.f16.f32 "
        "{%0,%1,%2,%3}, {%4,%5,%6,%7}, {%8,%9}, {%0,%1,%2,%3};"
        : "+f"(d[0]), "+f"(d[1]), "+f"(d[2]), "+f"(d[3])
        : "r"(a[0]), "r"(a[1]), "r"(a[2]), "r"(a[3]), "r"(b0), "r"(b1));
}

__device__ __forceinline__ void ldmx4(uint32_t* a, uint32_t addr) {
    asm volatile("ldmatrix.sync.aligned.m8n8.x4.shared.b16 {%0,%1,%2,%3}, [%4];"
                 : "=r"(a[0]), "=r"(a[1]), "=r"(a[2]), "=r"(a[3]) : "r"(addr));
}

// nibble pair (bits [0:8) of t) -> fp16x2 {1024+lo, 1024+hi}
__device__ __forceinline__ uint32_t dq(uint32_t t) {
    return (t & 0xFu) | ((t << 12) & 0xF0000u) | 0x64006400u;
}

// ---------------------------------------------------------------------------
__global__ void __launch_bounds__(256, 1) prep_kernel(const float* __restrict__ x) {
    int t = blockIdx.x, tid = threadIdx.x;
    float acc = 0.f;
    for (int k = tid; k < KTOT; k += 256) {
        float v = x[t * KTOT + k];
        __half h = __float2half(v);
        acc += __half2float(h);
        g_A[t * KTOT + k] = h;
    }
    __shared__ float red[8];
    #pragma unroll
    for (int off = 16; off; off >>= 1) acc += __shfl_down_sync(0xFFFFFFFFu, acc, off);
    if ((tid & 31) == 0) red[tid >> 5] = acc;
    __syncthreads();
    if (tid == 0) {
        float s = 0.f;
        #pragma unroll
        for (int i = 0; i < 8; i++) s += red[i];
        g_S[t] = s;
    }
}

// ---------------------------------------------------------------------------
__device__ __forceinline__ void issue_chunk(uint32_t sb, int tid, int n0, int c,
                                            const int* __restrict__ qw) {
    uint32_t stage = sb + SM_STAGE0 + (uint32_t)(c & (STAGES - 1)) * STAGE_BYTES;
    // A: 32 rows x 16 chunks of 16B, 512 segs
    #pragma unroll
    for (int i = 0; i < 2; i++) {
        int seg = tid + i * 256;
        int r = seg >> 4, cc = seg & 15;
        uint32_t dst = stage + r * 256 + (((uint32_t)cc ^ (uint32_t)(r & 7)) << 4);
        const char* src = (const char*)g_A + ((size_t)r * KTOT + (size_t)c * TILE_K) * 2 + cc * 16;
        CP16(dst, src);
    }
    // Q: 16 kwords x 32 segs of 16B (4 ints), 512 segs
    #pragma unroll
    for (int i = 0; i < 2; i++) {
        int seg = tid + i * 256;
        int kw = seg >> 5, ns = seg & 31;
        uint32_t dst = stage + 8192 + kw * 512 + ns * 16;
        const char* src = (const char*)qw + ((size_t)(c * 16 + kw) * NTOT + n0) * 4 + ns * 16;
        CP16(dst, src);
    }
    CP_COMMIT();
}

__global__ void __launch_bounds__(THREADS, 1) gemm_kernel(
    const int* __restrict__ qw, const float* __restrict__ scales,
    const float* __restrict__ zeros, const float* __restrict__ bias,
    float* __restrict__ out) {
    extern __shared__ __align__(1024) char smem[];
    uint32_t sb = smem_u32(smem);
    int tid = threadIdx.x, wid = tid >> 5, lane = tid & 31;
    int n0 = blockIdx.x * TILE_N;

    float* sc_sm   = (float*)(smem + SM_CONST);
    float* bi_sm   = sc_sm + 128;
    float* corr_sm = bi_sm + 128;
    float* S_sm    = corr_sm + 128;
    if (tid < 128) {
        float s = scales[n0 + tid];
        sc_sm[tid]   = s;
        bi_sm[tid]   = bias[n0 + tid];
        corr_sm[tid] = fmaf(1024.0f, s, zeros[n0 + tid]);
    }
    if (tid < 32) S_sm[tid] = g_S[tid];

    // prologue: 3 stages in flight
    issue_chunk(sb, tid, n0, 0, qw);
    issue_chunk(sb, tid, n0, 1, qw);
    issue_chunk(sb, tid, n0, 2, qw);

    const int lrow = lane & 15;        // ldmatrix row within m16
    const int lcb  = lane >> 4;        // ldmatrix col-block (0/1)
    const int j4   = lane & 3;         // k-pair within kword
    const int nrow = lane >> 2;        // n within n8 tile
    const int sh   = j4 * 8;

    float acc[2][2][4];
    #pragma unroll
    for (int mt = 0; mt < 2; mt++)
        #pragma unroll
        for (int j = 0; j < 2; j++)
            #pragma unroll
            for (int i = 0; i < 4; i++) acc[mt][j][i] = 0.f;

    for (int c = 0; c < NCHUNK; c++) {
        if (c < NCHUNK - 2)      asm volatile("cp.async.wait_group 2;" ::: "memory");
        else if (c == NCHUNK - 2) asm volatile("cp.async.wait_group 1;" ::: "memory");
        else                      asm volatile("cp.async.wait_group 0;" ::: "memory");
        __syncthreads();
        if (c + 3 < NCHUNK) issue_chunk(sb, tid, n0, c + 3, qw);

        uint32_t aBase = sb + SM_STAGE0 + (uint32_t)(c & (STAGES - 1)) * STAGE_BYTES;
        uint32_t qBase = aBase + 8192;
        uint32_t q0 = qBase + (uint32_t)(wid * 16 + nrow) * 4;       // j=0
        uint32_t q1 = q0 + 8 * 4;                                     // j=1

        #pragma unroll
        for (int kk = 0; kk < 8; kk++) {
            uint32_t a0[4], a1[4];
            uint32_t cc = (uint32_t)(kk * 2 + lcb);
            uint32_t ad0 = aBase + (uint32_t)lrow * 256 + ((cc ^ (uint32_t)(lrow & 7)) << 4);
            ldmx4(a0, ad0);
            ldmx4(a1, ad0 + 16 * 256);   // rows +16, same (r&7) -> same swizzle

            uint32_t w00, w01, w10, w11;
            asm volatile("ld.shared.b32 %0, [%1];" : "=r"(w00) : "r"(q0 + kk * 1024));
            asm volatile("ld.shared.b32 %0, [%1];" : "=r"(w01) : "r"(q0 + kk * 1024 + 512));
            asm volatile("ld.shared.b32 %0, [%1];" : "=r"(w10) : "r"(q1 + kk * 1024));
            asm volatile("ld.shared.b32 %0, [%1];" : "=r"(w11) : "r"(q1 + kk * 1024 + 512));

            uint32_t b00 = dq(w00 >> sh), b01 = dq(w01 >> sh);
            uint32_t b10 = dq(w10 >> sh), b11 = dq(w11 >> sh);

            mma16816(acc[0][0], a0, b00, b01);
            mma16816(acc[1][0], a1, b00, b01);
            mma16816(acc[0][1], a0, b10, b11);
            mma16816(acc[1][1], a1, b10, b11);
        }
    }

    // epilogue: y = s*D - S[r]*corr + b
    #pragma unroll
    for (int mt = 0; mt < 2; mt++) {
        #pragma unroll
        for (int j = 0; j < 2; j++) {
            int ncl = wid * 16 + j * 8 + j4 * 2;       // local col (even)
            float s0 = sc_sm[ncl],     s1 = sc_sm[ncl + 1];
            float b0 = bi_sm[ncl],     b1 = bi_sm[ncl + 1];
            float c0 = corr_sm[ncl],   c1 = corr_sm[ncl + 1];
            int r0 = mt * 16 + nrow;
            int r1 = r0 + 8;
            float S0 = S_sm[r0], S1 = S_sm[r1];
            float2 y0, y1;
            y0.x = fmaf(s0, acc[mt][j][0], b0) - S0 * c0;
            y0.y = fmaf(s1, acc[mt][j][1], b1) - S0 * c1;
            y1.x = fmaf(s0, acc[mt][j][2], b0) - S1 * c0;
            y1.y = fmaf(s1, acc[mt][j][3], b1) - S1 * c1;
            *(float2*)(out + (size_t)r0 * NTOT + n0 + ncl) = y0;
            *(float2*)(out + (size_t)r1 * NTOT + n0 + ncl) = y1;
        }
    }
}

// ---------------------------------------------------------------------------
extern "C" void kernel_launch(void* const* d_in, const int* in_sizes, int n_in,
                              void* d_out, int out_size) {
    const float* x      = (const float*)d_in[0];
    const int*   qw     = (const int*)d_in[1];
    const float* scales = (const float*)d_in[2];
    const float* zeros  = (const float*)d_in[3];
    const float* bias   = (const float*)d_in[4];
    float* out = (float*)d_out;

    cudaFuncSetAttribute(gemm_kernel, cudaFuncAttributeMaxDynamicSharedMemorySize, SMEM_TOTAL);

    prep_kernel<<<MTOK, 256>>>(x);
    gemm_kernel<<<NTOT / TILE_N, THREADS, SMEM_TOTAL>>>(qw, scales, zeros, bias, out);
}

// round 4
// speedup vs baseline: 1.3406x; 1.3406x over previous
#include <cuda_runtime.h>
#include <cuda_fp16.h>
#include <cstdint>

// ============================================================================
// QuantLinear: y = x @ (scales*q - zeros) + bias        (sm_100 portable path)
//   x:[32,4096] f32, qweight:[512,11008] i32 (8 nibbles/word along K),
//   scales/zeros/bias:[11008] f32, out:[32,11008] f32
//
//   prep:  g_A[32,4096] = fp16(x), columns permuted within groups of 8 as
//          (0,4,1,5,2,6,3,7); per-block partial row sums -> g_Spart[128].
//   init:  out = bias - S*(1024*scale + zeros)   (S = sum of fp16(x) per row)
//   gemm:  grid (86,4): N tiles of 128 x K splits of 1024. mma.m16n8k16
//          fp16->f32. B dequant: thread j4 takes ((w>>4*j4)&0x000F000F)|0x6400
//          6400 -> fp16x2 {1024+n_lo,1024+n_hi} directly in fragment layout
//          (permutation makes nibble pair (j4, j4+4) the right k-pair).
//          Epilogue: atomicAdd(out, s*D_partial).
// ============================================================================

#define KTOT   4096
#define NTOT   11008
#define MTOK   32
#define TILE_N 128
#define TILE_K 128
#define KSPLIT 4
#define CCHUNK 8                  // chunks per CTA = (KTOT/TILE_K)/KSPLIT
#define THREADS 256
#define STAGES 3

#define STAGE_BYTES 16384         // A 8192 + Q 8192
#define SMEM_TOTAL (STAGES * STAGE_BYTES)   // 49152

__device__ __half g_A[MTOK * KTOT];
__device__ float  g_Spart[128];   // 4 partials per token

// ---------------------------------------------------------------------------
__device__ __forceinline__ uint32_t smem_u32(const void* p) {
    uint32_t a;
    asm("{ .reg .u64 t; cvta.to.shared.u64 t, %1; cvt.u32.u64 %0, t; }"
        : "=r"(a) : "l"(p));
    return a;
}

#define CP16(dst, src) \
    asm volatile("cp.async.cg.shared.global [%0], [%1], 16;" :: "r"(dst), "l"(src))
#define CP_COMMIT() asm volatile("cp.async.commit_group;" ::: "memory")

__device__ __forceinline__ void mma16816(float* d, const uint32_t* a,
                                         uint32_t b0, uint32_t b1) {
    asm volatile(
        "mma.sync.aligned.m16n8k16.row.col.f32.f16.f16.f32 "
        "{%0,%1,%2,%3}, {%4,%5,%6,%7}, {%8,%9}, {%0,%1,%2,%3};"
        : "+f"(d[0]), "+f"(d[1]), "+f"(d[2]), "+f"(d[3])
        : "r"(a[0]), "r"(a[1]), "r"(a[2]), "r"(a[3]), "r"(b0), "r"(b1));
}

__device__ __forceinline__ void ldmx4(uint32_t* a, uint32_t addr) {
    asm volatile("ldmatrix.sync.aligned.m8n8.x4.shared.b16 {%0,%1,%2,%3}, [%4];"
                 : "=r"(a[0]), "=r"(a[1]), "=r"(a[2]), "=r"(a[3]) : "r"(addr));
}

// ---------------------------------------------------------------------------
// prep: 128 blocks = 32 tokens x 4 K-slices of 1024
// ---------------------------------------------------------------------------
__global__ void __launch_bounds__(256, 2) prep_kernel(const float* __restrict__ x) {
    int t = blockIdx.x >> 2, sl = blockIdx.x & 3, tid = threadIdx.x;
    int k0 = sl * 1024 + tid * 4;
    float4 v = *(const float4*)(x + (size_t)t * KTOT + k0);
    float acc = 0.f;
    float vv[4] = {v.x, v.y, v.z, v.w};
    #pragma unroll
    for (int j = 0; j < 4; j++) {
        int k = k0 + j;
        __half h = __float2half(vv[j]);
        acc += __half2float(h);
        int jj = k & 7;
        int kd = (k & ~7) + ((jj & 3) * 2 + (jj >> 2));
        g_A[t * KTOT + kd] = h;
    }
    __shared__ float red[8];
    #pragma unroll
    for (int off = 16; off; off >>= 1) acc += __shfl_down_sync(0xFFFFFFFFu, acc, off);
    if ((tid & 31) == 0) red[tid >> 5] = acc;
    __syncthreads();
    if (tid == 0) {
        float s = 0.f;
        #pragma unroll
        for (int i = 0; i < 8; i++) s += red[i];
        g_Spart[blockIdx.x] = s;
    }
}

// ---------------------------------------------------------------------------
// init: out = bias - S*(1024*scale + zeros)    (344 blocks x 256 thr x 4 elems)
// ---------------------------------------------------------------------------
__global__ void __launch_bounds__(256, 2) init_kernel(
    const float* __restrict__ scales, const float* __restrict__ zeros,
    const float* __restrict__ bias, float* __restrict__ out) {
    int gid = blockIdx.x * 256 + threadIdx.x;
    int f = gid * 4;
    int t = f / NTOT;
    int n = f - t * NTOT;
    float S = g_Spart[t * 4] + g_Spart[t * 4 + 1] + g_Spart[t * 4 + 2] + g_Spart[t * 4 + 3];
    float4 s4 = *(const float4*)(scales + n);
    float4 z4 = *(const float4*)(zeros + n);
    float4 b4 = *(const float4*)(bias + n);
    float4 o;
    o.x = b4.x - S * fmaf(1024.f, s4.x, z4.x);
    o.y = b4.y - S * fmaf(1024.f, s4.y, z4.y);
    o.z = b4.z - S * fmaf(1024.f, s4.z, z4.z);
    o.w = b4.w - S * fmaf(1024.f, s4.w, z4.w);
    *(float4*)(out + f) = o;
}

// ---------------------------------------------------------------------------
// gemm
// ---------------------------------------------------------------------------
__device__ __forceinline__ void issue_chunk(uint32_t sb, int tid, int n0,
                                            int slot, int cg,
                                            const int* __restrict__ qw) {
    uint32_t stage = sb + (uint32_t)slot * STAGE_BYTES;
    // A: 32 rows x 16 chunks of 16B (swizzled)
    #pragma unroll
    for (int i = 0; i < 2; i++) {
        int seg = tid + i * 256;
        int r = seg >> 4, cc = seg & 15;
        uint32_t dst = stage + r * 256 + (((uint32_t)cc ^ (uint32_t)(r & 7)) << 4);
        const char* src = (const char*)g_A + ((size_t)r * KTOT + (size_t)cg * TILE_K) * 2 + cc * 16;
        CP16(dst, src);
    }
    // Q: 16 kwords x 32 segs of 16B
    #pragma unroll
    for (int i = 0; i < 2; i++) {
        int seg = tid + i * 256;
        int kw = seg >> 5, ns = seg & 31;
        uint32_t dst = stage + 8192 + kw * 512 + ns * 16;
        const char* src = (const char*)qw + ((size_t)(cg * 16 + kw) * NTOT + n0) * 4 + ns * 16;
        CP16(dst, src);
    }
    CP_COMMIT();
}

__global__ void __launch_bounds__(THREADS, 2) gemm_kernel(
    const int* __restrict__ qw, const float* __restrict__ scales,
    float* __restrict__ out) {
    extern __shared__ __align__(1024) char smem[];
    uint32_t sb = smem_u32(smem);
    int tid = threadIdx.x, wid = tid >> 5, lane = tid & 31;
    int n0 = blockIdx.x * TILE_N;
    int kb = blockIdx.y * CCHUNK;

    issue_chunk(sb, tid, n0, 0, kb + 0, qw);
    issue_chunk(sb, tid, n0, 1, kb + 1, qw);

    const int lrow = lane & 15;
    const int lcb  = lane >> 4;
    const int j4   = lane & 3;
    const int nrow = lane >> 2;
    const uint32_t sh4 = (uint32_t)(j4 * 4);

    float acc[2][2][4];
    #pragma unroll
    for (int mt = 0; mt < 2; mt++)
        #pragma unroll
        for (int j = 0; j < 2; j++)
            #pragma unroll
            for (int i = 0; i < 4; i++) acc[mt][j][i] = 0.f;

    for (int c = 0; c < CCHUNK; c++) {
        if (c < CCHUNK - 1) asm volatile("cp.async.wait_group 1;" ::: "memory");
        else                asm volatile("cp.async.wait_group 0;" ::: "memory");
        __syncthreads();
        if (c + 2 < CCHUNK) issue_chunk(sb, tid, n0, (c + 2) % STAGES, kb + c + 2, qw);

        uint32_t aBase = sb + (uint32_t)(c % STAGES) * STAGE_BYTES;
        uint32_t qBase = aBase + 8192;
        uint32_t q0 = qBase + (uint32_t)(wid * 16 + nrow) * 4;   // j=0 n-slice
        uint32_t q1 = q0 + 8 * 4;                                 // j=1 n-slice

        #pragma unroll
        for (int kk = 0; kk < 8; kk++) {
            uint32_t a0[4], a1[4];
            uint32_t cc = (uint32_t)(kk * 2 + lcb);
            uint32_t ad0 = aBase + (uint32_t)lrow * 256 + ((cc ^ (uint32_t)(lrow & 7)) << 4);
            ldmx4(a0, ad0);
            ldmx4(a1, ad0 + 16 * 256);

            uint32_t w00, w01, w10, w11;
            asm volatile("ld.shared.b32 %0, [%1];" : "=r"(w00) : "r"(q0 + kk * 1024));
            asm volatile("ld.shared.b32 %0, [%1];" : "=r"(w01) : "r"(q0 + kk * 1024 + 512));
            asm volatile("ld.shared.b32 %0, [%1];" : "=r"(w10) : "r"(q1 + kk * 1024));
            asm volatile("ld.shared.b32 %0, [%1];" : "=r"(w11) : "r"(q1 + kk * 1024 + 512));

            // permuted dequant: pair (j4, j4+4) -> fp16x2 {1024+lo, 1024+hi}
            uint32_t b00 = ((w00 >> sh4) & 0x000F000Fu) | 0x64006400u;
            uint32_t b01 = ((w01 >> sh4) & 0x000F000Fu) | 0x64006400u;
            uint32_t b10 = ((w10 >> sh4) & 0x000F000Fu) | 0x64006400u;
            uint32_t b11 = ((w11 >> sh4) & 0x000F000Fu) | 0x64006400u;

            mma16816(acc[0][0], a0, b00, b01);
            mma16816(acc[1][0], a1, b00, b01);
            mma16816(acc[0][1], a0, b10, b11);
            mma16816(acc[1][1], a1, b10, b11);
        }
    }

    // epilogue: out += s * D_partial
    #pragma unroll
    for (int mt = 0; mt < 2; mt++) {
        #pragma unroll
        for (int j = 0; j < 2; j++) {
            int ncl = wid * 16 + j * 8 + j4 * 2;
            int col = n0 + ncl;
            float s0 = __ldg(scales + col), s1 = __ldg(scales + col + 1);
            int r0 = mt * 16 + nrow;
            int r1 = r0 + 8;
            atomicAdd(out + (size_t)r0 * NTOT + col,     s0 * acc[mt][j][0]);
            atomicAdd(out + (size_t)r0 * NTOT + col + 1, s1 * acc[mt][j][1]);
            atomicAdd(out + (size_t)r1 * NTOT + col,     s0 * acc[mt][j][2]);
            atomicAdd(out + (size_t)r1 * NTOT + col + 1, s1 * acc[mt][j][3]);
        }
    }
}

// ---------------------------------------------------------------------------
extern "C" void kernel_launch(void* const* d_in, const int* in_sizes, int n_in,
                              void* d_out, int out_size) {
    const float* x      = (const float*)d_in[0];
    const int*   qw     = (const int*)d_in[1];
    const float* scales = (const float*)d_in[2];
    const float* zeros  = (const float*)d_in[3];
    const float* bias   = (const float*)d_in[4];
    float* out = (float*)d_out;

    cudaFuncSetAttribute(gemm_kernel, cudaFuncAttributeMaxDynamicSharedMemorySize, SMEM_TOTAL);

    prep_kernel<<<128, 256>>>(x);
    init_kernel<<<344, 256>>>(scales, zeros, bias, out);
    gemm_kernel<<<dim3(NTOT / TILE_N, KSPLIT), THREADS, SMEM_TOTAL>>>(qw, scales, out);
}

// round 6
// speedup vs baseline: 1.4034x; 1.0469x over previous
#include <cuda_runtime.h>
#include <cuda_fp16.h>
#include <cstdint>

// ============================================================================
// QuantLinear: y = x @ (scales*q - zeros) + bias        (sm_100 portable path)
//   x:[32,4096] f32, qweight:[512,11008] i32 (8 nibbles/word along K),
//   scales/zeros/bias:[11008] f32, out:[32,11008] f32
//
//   prep:  g_A[32,4096] = fp16(x), columns permuted within groups of 8 as
//          (0,4,1,5,2,6,3,7) IN REGISTERS, 16B coalesced stores;
//          per-block partial row sums -> g_Spart[128].
//   init:  out = bias - S*(1024*scale + zeros)
//   gemm:  grid (86,3): N tiles of 128 x K splits of 11/11/10 chunks (one
//          wave at 2 CTAs/SM). mma.m16n8k16 fp16->f32, B dequant 2 LOP-ops
//          per fragment reg. Epilogue: atomicAdd(out, s*D_partial).
// ============================================================================

#define KTOT   4096
#define NTOT   11008
#define MTOK   32
#define TILE_N 128
#define TILE_K 128
#define KSPLIT 3
#define THREADS 256
#define STAGES 3

#define STAGE_BYTES 16384         // A 8192 + Q 8192
#define SMEM_TOTAL (STAGES * STAGE_BYTES)   // 49152

__device__ __half g_A[MTOK * KTOT];
__device__ float  g_Spart[128];   // 4 partials per token

// ---------------------------------------------------------------------------
__device__ __forceinline__ uint32_t smem_u32(const void* p) {
    uint32_t a;
    asm("{ .reg .u64 t; cvta.to.shared.u64 t, %1; cvt.u32.u64 %0, t; }"
        : "=r"(a) : "l"(p));
    return a;
}

#define CP16(dst, src) \
    asm volatile("cp.async.cg.shared.global [%0], [%1], 16;" :: "r"(dst), "l"(src))
#define CP_COMMIT() asm volatile("cp.async.commit_group;" ::: "memory")

__device__ __forceinline__ void mma16816(float* d, const uint32_t* a,
                                         uint32_t b0, uint32_t b1) {
    asm volatile(
        "mma.sync.aligned.m16n8k16.row.col.f32.f16.f16.f32 "
        "{%0,%1,%2,%3}, {%4,%5,%6,%7}, {%8,%9}, {%0,%1,%2,%3};"
        : "+f"(d[0]), "+f"(d[1]), "+f"(d[2]), "+f"(d[3])
        : "r"(a[0]), "r"(a[1]), "r"(a[2]), "r"(a[3]), "r"(b0), "r"(b1));
}

__device__ __forceinline__ void ldmx4(uint32_t* a, uint32_t addr) {
    asm volatile("ldmatrix.sync.aligned.m8n8.x4.shared.b16 {%0,%1,%2,%3}, [%4];"
                 : "=r"(a[0]), "=r"(a[1]), "=r"(a[2]), "=r"(a[3]) : "r"(addr));
}

// ---------------------------------------------------------------------------
// prep: 128 blocks (32 tokens x 4 slices) x 128 threads; thread = one group
// of 8 k-values -> permute in registers, one 16B coalesced store.
// ---------------------------------------------------------------------------
__global__ void __launch_bounds__(128, 4) prep_kernel(const float* __restrict__ x) {
    int t = blockIdx.x >> 2, sl = blockIdx.x & 3, tid = threadIdx.x;
    int k0 = sl * 1024 + tid * 8;
    const float4* src = (const float4*)(x + (size_t)t * KTOT + k0);
    float4 v0 = src[0];
    float4 v1 = src[1];
    __half h0 = __float2half(v0.x), h1 = __float2half(v0.y);
    __half h2 = __float2half(v0.z), h3 = __float2half(v0.w);
    __half h4 = __float2half(v1.x), h5 = __float2half(v1.y);
    __half h6 = __float2half(v1.z), h7 = __float2half(v1.w);
    float acc = __half2float(h0) + __half2float(h1) + __half2float(h2) +
                __half2float(h3) + __half2float(h4) + __half2float(h5) +
                __half2float(h6) + __half2float(h7);
    // interleave: dest = {h0,h4, h1,h5, h2,h6, h3,h7}
    uint4 o;
    o.x = (uint32_t)__half_as_ushort(h0) | ((uint32_t)__half_as_ushort(h4) << 16);
    o.y = (uint32_t)__half_as_ushort(h1) | ((uint32_t)__half_as_ushort(h5) << 16);
    o.z = (uint32_t)__half_as_ushort(h2) | ((uint32_t)__half_as_ushort(h6) << 16);
    o.w = (uint32_t)__half_as_ushort(h3) | ((uint32_t)__half_as_ushort(h7) << 16);
    *(uint4*)(g_A + (size_t)t * KTOT + k0) = o;

    __shared__ float red[4];
    #pragma unroll
    for (int off = 16; off; off >>= 1) acc += __shfl_down_sync(0xFFFFFFFFu, acc, off);
    if ((tid & 31) == 0) red[tid >> 5] = acc;
    __syncthreads();
    if (tid == 0)
        g_Spart[blockIdx.x] = red[0] + red[1] + red[2] + red[3];
}

// ---------------------------------------------------------------------------
// init: out = bias - S*(1024*scale + zeros)    (344 blocks x 256 thr x 4 elems)
// ---------------------------------------------------------------------------
__global__ void __launch_bounds__(256, 2) init_kernel(
    const float* __restrict__ scales, const float* __restrict__ zeros,
    const float* __restrict__ bias, float* __restrict__ out) {
    int gid = blockIdx.x * 256 + threadIdx.x;
    int f = gid * 4;
    int t = f / NTOT;
    int n = f - t * NTOT;
    float S = g_Spart[t * 4] + g_Spart[t * 4 + 1] + g_Spart[t * 4 + 2] + g_Spart[t * 4 + 3];
    float4 s4 = *(const float4*)(scales + n);
    float4 z4 = *(const float4*)(zeros + n);
    float4 b4 = *(const float4*)(bias + n);
    float4 o;
    o.x = b4.x - S * fmaf(1024.f, s4.x, z4.x);
    o.y = b4.y - S * fmaf(1024.f, s4.y, z4.y);
    o.z = b4.z - S * fmaf(1024.f, s4.z, z4.z);
    o.w = b4.w - S * fmaf(1024.f, s4.w, z4.w);
    *(float4*)(out + f) = o;
}

// ---------------------------------------------------------------------------
// gemm
// ---------------------------------------------------------------------------
__device__ __forceinline__ void issue_chunk(uint32_t sb, int tid, int n0,
                                            int slot, int cg,
                                            const int* __restrict__ qw) {
    uint32_t stage = sb + (uint32_t)slot * STAGE_BYTES;
    // A: 32 rows x 16 chunks of 16B (swizzled)
    #pragma unroll
    for (int i = 0; i < 2; i++) {
        int seg = tid + i * 256;
        int r = seg >> 4, cc = seg & 15;
        uint32_t dst = stage + r * 256 + (((uint32_t)cc ^ (uint32_t)(r & 7)) << 4);
        const char* src = (const char*)g_A + ((size_t)r * KTOT + (size_t)cg * TILE_K) * 2 + cc * 16;
        CP16(dst, src);
    }
    // Q: 16 kwords x 32 segs of 16B
    #pragma unroll
    for (int i = 0; i < 2; i++) {
        int seg = tid + i * 256;
        int kw = seg >> 5, ns = seg & 31;
        uint32_t dst = stage + 8192 + kw * 512 + ns * 16;
        const char* src = (const char*)qw + ((size_t)(cg * 16 + kw) * NTOT + n0) * 4 + ns * 16;
        CP16(dst, src);
    }
    CP_COMMIT();
}

__global__ void __launch_bounds__(THREADS, 2) gemm_kernel(
    const int* __restrict__ qw, const float* __restrict__ scales,
    float* __restrict__ out) {
    extern __shared__ __align__(1024) char smem[];
    uint32_t sb = smem_u32(smem);
    int tid = threadIdx.x, wid = tid >> 5, lane = tid & 31;
    int n0 = blockIdx.x * TILE_N;
    int kb = blockIdx.y * 11;                       // splits: 11 / 11 / 10
    int nc = (blockIdx.y == 2) ? 10 : 11;

    issue_chunk(sb, tid, n0, 0, kb + 0, qw);
    issue_chunk(sb, tid, n0, 1, kb + 1, qw);

    const int lrow = lane & 15;
    const int lcb  = lane >> 4;
    const int j4   = lane & 3;
    const int nrow = lane >> 2;
    const uint32_t sh4 = (uint32_t)(j4 * 4);

    float acc[2][2][4];
    #pragma unroll
    for (int mt = 0; mt < 2; mt++)
        #pragma unroll
        for (int j = 0; j < 2; j++)
            #pragma unroll
            for (int i = 0; i < 4; i++) acc[mt][j][i] = 0.f;

    for (int c = 0; c < nc; c++) {
        if (c < nc - 1) asm volatile("cp.async.wait_group 1;" ::: "memory");
        else            asm volatile("cp.async.wait_group 0;" ::: "memory");
        __syncthreads();
        if (c + 2 < nc) issue_chunk(sb, tid, n0, (c + 2) % STAGES, kb + c + 2, qw);

        uint32_t aBase = sb + (uint32_t)(c % STAGES) * STAGE_BYTES;
        uint32_t qBase = aBase + 8192;
        uint32_t q0 = qBase + (uint32_t)(wid * 16 + nrow) * 4;   // j=0 n-slice
        uint32_t q1 = q0 + 8 * 4;                                 // j=1 n-slice

        #pragma unroll
        for (int kk = 0; kk < 8; kk++) {
            uint32_t a0[4], a1[4];
            uint32_t cc = (uint32_t)(kk * 2 + lcb);
            uint32_t ad0 = aBase + (uint32_t)lrow * 256 + ((cc ^ (uint32_t)(lrow & 7)) << 4);
            ldmx4(a0, ad0);
            ldmx4(a1, ad0 + 16 * 256);

            uint32_t w00, w01, w10, w11;
            asm volatile("ld.shared.b32 %0, [%1];" : "=r"(w00) : "r"(q0 + kk * 1024));
            asm volatile("ld.shared.b32 %0, [%1];" : "=r"(w01) : "r"(q0 + kk * 1024 + 512));
            asm volatile("ld.shared.b32 %0, [%1];" : "=r"(w10) : "r"(q1 + kk * 1024));
            asm volatile("ld.shared.b32 %0, [%1];" : "=r"(w11) : "r"(q1 + kk * 1024 + 512));

            // permuted dequant: pair (j4, j4+4) -> fp16x2 {1024+lo, 1024+hi}
            uint32_t b00 = ((w00 >> sh4) & 0x000F000Fu) | 0x64006400u;
            uint32_t b01 = ((w01 >> sh4) & 0x000F000Fu) | 0x64006400u;
            uint32_t b10 = ((w10 >> sh4) & 0x000F000Fu) | 0x64006400u;
            uint32_t b11 = ((w11 >> sh4) & 0x000F000Fu) | 0x64006400u;

            mma16816(acc[0][0], a0, b00, b01);
            mma16816(acc[1][0], a1, b00, b01);
            mma16816(acc[0][1], a0, b10, b11);
            mma16816(acc[1][1], a1, b10, b11);
        }
    }

    // epilogue: out += s * D_partial
    #pragma unroll
    for (int mt = 0; mt < 2; mt++) {
        #pragma unroll
        for (int j = 0; j < 2; j++) {
            int ncl = wid * 16 + j * 8 + j4 * 2;
            int col = n0 + ncl;
            float s0 = __ldg(scales + col), s1 = __ldg(scales + col + 1);
            int r0 = mt * 16 + nrow;
            int r1 = r0 + 8;
            atomicAdd(out + (size_t)r0 * NTOT + col,     s0 * acc[mt][j][0]);
            atomicAdd(out + (size_t)r0 * NTOT + col + 1, s1 * acc[mt][j][1]);
            atomicAdd(out + (size_t)r1 * NTOT + col,     s0 * acc[mt][j][2]);
            atomicAdd(out + (size_t)r1 * NTOT + col + 1, s1 * acc[mt][j][3]);
        }
    }
}

// ---------------------------------------------------------------------------
extern "C" void kernel_launch(void* const* d_in, const int* in_sizes, int n_in,
                              void* d_out, int out_size) {
    const float* x      = (const float*)d_in[0];
    const int*   qw     = (const int*)d_in[1];
    const float* scales = (const float*)d_in[2];
    const float* zeros  = (const float*)d_in[3];
    const float* bias   = (const float*)d_in[4];
    float* out = (float*)d_out;

    cudaFuncSetAttribute(gemm_kernel, cudaFuncAttributeMaxDynamicSharedMemorySize, SMEM_TOTAL);

    prep_kernel<<<128, 128>>>(x);
    init_kernel<<<344, 256>>>(scales, zeros, bias, out);
    gemm_kernel<<<dim3(NTOT / TILE_N, KSPLIT), THREADS, SMEM_TOTAL>>>(qw, scales, out);
}